// round 14
// baseline (speedup 1.0000x reference)
#include <cuda_runtime.h>
#include <cuda_bf16.h>
#include <stdint.h>

typedef unsigned long long ull;

// Problem constants
#define BB    16
#define NN    100000
#define CC    30
#define NC    (NN * CC)           // 3,000,000
#define TOT   (BB * NC)           // 48,000,000
#define PAIRS (BB * CC)           // 480
#define CAP   512                 // candidate buffer per (b,c)
#define PRE   200                 // PRE_NMS_TOPK
#define MAXDET 100
#define NWORDS 7                  // ceil(200/32)
#define NWP    8                  // padded row stride (words)
#define BOXPAD 224                // padded box count (NWORDS*32)
#define MPC    16                 // merge candidates per class
#define SCAN_BLOCKS 4096
#define NTW   512                 // wide block for pair/merge kernels

#define COLLECT_T    0.997f
#define SCORE_T      0.01f
#define NMS_T        0.5f

// Output layout (flattened float32 concat of the 5 outputs)
#define OUT_BOXES  0
#define OUT_SCORES (BB * MAXDET * 4)
#define OUT_LABELS (OUT_SCORES + BB * MAXDET)
#define OUT_ROT    (OUT_LABELS + BB * MAXDET)
#define OUT_TR     (OUT_ROT + BB * MAXDET * 3)

// Scratch (device globals; zero-initialized at module load)
__device__ ull g_cand[PAIRS * CAP];
__device__ int g_cnt[PAIRS];
__device__ ull g_ckey[PAIRS * PRE];   // survivors by compacted rank
__device__ int g_nidx[PAIRS * PRE];   // anchor index keyed by ORIGINAL rank
__device__ int g_scnt[PAIRS];

// ---------------------------------------------------------------------------
// Pass 1: stream classification, append candidates with score > COLLECT_T.
__device__ __forceinline__ void scan_proc(float4 v, int i4) {
    float m = fmaxf(fmaxf(v.x, v.y), fmaxf(v.z, v.w));
    if (m > COLLECT_T) {
        int base = i4 * 4;
        float vs[4] = {v.x, v.y, v.z, v.w};
#pragma unroll
        for (int k = 0; k < 4; k++) {
            float s = vs[k];
            if (s > COLLECT_T) {
                int i = base + k;
                int b = i / NC;
                int r = i - b * NC;
                int n = r / CC;
                int c = r - n * CC;
                int pair = b * CC + c;
                int pos = atomicAdd(&g_cnt[pair], 1);
                if (pos < CAP) {
                    g_cand[pair * CAP + pos] =
                        ((ull)__float_as_uint(s) << 32) | (unsigned)(~n);
                }
            }
        }
    }
}

__global__ void k_scan(const float* __restrict__ cls) {
    const float4* c4 = reinterpret_cast<const float4*>(cls);
    const int NIT = TOT / 4;
    int T = gridDim.x * blockDim.x;
    int i = blockIdx.x * blockDim.x + threadIdx.x;
    // Unroll-8 main pass: 8 independent LDG.128 in flight per thread.
    for (; i + 7 * T < NIT; i += 8 * T) {
        float4 v0 = __ldg(&c4[i]);
        float4 v1 = __ldg(&c4[i + T]);
        float4 v2 = __ldg(&c4[i + 2 * T]);
        float4 v3 = __ldg(&c4[i + 3 * T]);
        float4 v4 = __ldg(&c4[i + 4 * T]);
        float4 v5 = __ldg(&c4[i + 5 * T]);
        float4 v6 = __ldg(&c4[i + 6 * T]);
        float4 v7 = __ldg(&c4[i + 7 * T]);
        scan_proc(v0, i);
        scan_proc(v1, i + T);
        scan_proc(v2, i + 2 * T);
        scan_proc(v3, i + 3 * T);
        scan_proc(v4, i + 4 * T);
        scan_proc(v5, i + 5 * T);
        scan_proc(v6, i + 6 * T);
        scan_proc(v7, i + 7 * T);
    }
    // Unroll-4 mop-up.
    for (; i + 3 * T < NIT; i += 4 * T) {
        float4 a = __ldg(&c4[i]);
        float4 b = __ldg(&c4[i + T]);
        float4 c = __ldg(&c4[i + 2 * T]);
        float4 d = __ldg(&c4[i + 3 * T]);
        scan_proc(a, i);
        scan_proc(b, i + T);
        scan_proc(c, i + 2 * T);
        scan_proc(d, i + 3 * T);
    }
    // Predicated tail: residual loads issued independently (MLP-3).
    {
        bool va = (i < NIT);
        bool vb = (i + T < NIT);
        bool vc = (i + 2 * T < NIT);
        float4 a, b, c;
        if (va) a = __ldg(&c4[i]);
        if (vb) b = __ldg(&c4[i + T]);
        if (vc) c = __ldg(&c4[i + 2 * T]);
        if (va) scan_proc(a, i);
        if (vb) scan_proc(b, i + T);
        if (vc) scan_proc(c, i + 2 * T);
    }
}

// ---------------------------------------------------------------------------
// Bitonic sort of 512 u64 keys with 512 threads, ONE element per thread.
// After return, v = key at rank tid (descending). Ping-pong buffers give
// ONE __syncthreads per smem stage: a later write to buffer X cannot race an
// earlier read of X because that read happens-before the intervening stage's
// sync, which all threads passed.
__device__ __forceinline__ void sort512w(ull& v, ull* bufA, ull* bufB, int tid) {
    int pp = 0;
#pragma unroll
    for (int k2 = 2; k2 <= 512; k2 <<= 1) {
#pragma unroll
        for (int j = k2 >> 1; j > 0; j >>= 1) {
            bool up = (tid & j) != 0;
            bool d  = ((tid & k2) == 0);
            ull o;
            if (j >= 32) {
                ull* buf = pp ? bufB : bufA;
                buf[tid] = v;
                __syncthreads();
                o = buf[tid ^ j];
                pp ^= 1;
            } else {
                o = __shfl_xor_sync(0xFFFFFFFFu, v, j);
            }
            v = (up == d) ? (v < o ? v : o) : (v > o ? v : o);
        }
    }
}

// ---------------------------------------------------------------------------
// Pass 2: per (b,c): exact top-200 sort + greedy NMS + compaction. 512 thr.
__global__ void __launch_bounds__(NTW)
k_pair(const float* __restrict__ boxes, const float* __restrict__ cls) {
    __shared__ ull     s_x[CAP];
    __shared__ ull     s_y[CAP];
    __shared__ ull     s_keys[PRE];
    __shared__ float4  s_box[BOXPAD];
    __shared__ float   s_ar[BOXPAD];
    __shared__ unsigned s_sup[BOXPAD * NWP];
    __shared__ unsigned s_keep[NWORDS];
    __shared__ int     s_M;

    int tid  = threadIdx.x;
    int pair = blockIdx.x;
    int b    = pair / CC;
    int c    = pair - b * CC;

    if (tid == 0) { s_M = g_cnt[pair]; g_cnt[pair] = 0; }
    __syncthreads();
    int M = s_M;

    if (M >= PRE && M <= CAP) {
        ull v = (tid < M) ? g_cand[pair * CAP + tid] : 0ULL;
        sort512w(v, s_x, s_y, tid);
        if (tid < PRE) s_keys[tid] = v;
    } else {
        // Exact fallback (statistically never taken): repeated bounded
        // argmax over the full column with the reference SCORE_T mask.
        ull prev = 0xFFFFFFFFFFFFFFFFULL;
        for (int k = 0; k < PRE; k++) {
            ull best = 0ULL;
            for (int n = tid; n < NN; n += NTW) {
                float s = cls[(size_t)(b * NN + n) * CC + c];
                if (s > SCORE_T) {
                    ull key = ((ull)__float_as_uint(s) << 32) | (unsigned)(~n);
                    if (key < prev && key > best) best = key;
                }
            }
            s_x[tid] = best;
            __syncthreads();
            for (int st = 256; st > 0; st >>= 1) {
                if (tid < st && s_x[tid + st] > s_x[tid]) s_x[tid] = s_x[tid + st];
                __syncthreads();
            }
            if (tid == 0) s_keys[k] = s_x[0];
            prev = s_x[0];
            __syncthreads();
        }
    }
    __syncthreads();

    // Gather top-200 boxes; pad rows [PRE, BOXPAD) with zero-boxes.
    // A zero-box never produces a suppression bit: inter = 0, and
    // 0 > 0.5*max(uni, 1e-8) is false — so the padded columns are inert
    // and the per-iteration j<PRE check can be dropped.
    if (tid < BOXPAD) {
        ull key = (tid < PRE) ? s_keys[tid] : 0ULL;
        if (key != 0ULL) {
            unsigned n = ~(unsigned)(key & 0xFFFFFFFFULL);
            const float4* bp = reinterpret_cast<const float4*>(boxes);
            float4 bx = __ldg(&bp[(size_t)b * NN + n]);
            s_box[tid] = bx;
            s_ar[tid]  = fmaxf(bx.z - bx.x, 0.f) * fmaxf(bx.w - bx.y, 0.f);
        } else {
            s_box[tid] = make_float4(0.f, 0.f, 0.f, 0.f);
            s_ar[tid]  = 0.f;
        }
    }
    __syncthreads();

    // Suppression bit matrix: bit (i, j) iff j>i && j<PRE && iou>0.5.
    // 872 flat (word, row) tasks with w >= row>>5. Division-free hot loop:
    // iou > 0.5 <=> inter > 0.5*u exactly, except the 1-ulp window where the
    // rounded division may land on exactly 0.5; those rare bits are collected
    // in wordB and re-resolved with the original exact-division expression.
    // j>i applied as a post-loop mask on diagonal words only.
    for (int t = tid; t < 872; t += NTW) {
        int w, i;
        if      (t < 32)  { w = 0; i = t; }
        else if (t < 96)  { w = 1; i = t - 32; }
        else if (t < 192) { w = 2; i = t - 96; }
        else if (t < 320) { w = 3; i = t - 192; }
        else if (t < 480) { w = 4; i = t - 320; }
        else if (t < 672) { w = 5; i = t - 480; }
        else              { w = 6; i = t - 672; }
        float4 bi = s_box[i];
        float ai = s_ar[i];
        unsigned wordA = 0u, wordB = 0u;
        int jbase = w * 32;
#pragma unroll 4
        for (int jj = 0; jj < 32; jj++) {
            int j = jbase + jj;
            float4 bj = s_box[j];
            float xx1 = fmaxf(bi.x, bj.x);
            float yy1 = fmaxf(bi.y, bj.y);
            float xx2 = fminf(bi.z, bj.z);
            float yy2 = fminf(bi.w, bj.w);
            float inter = fmaxf(xx2 - xx1, 0.f) * fmaxf(yy2 - yy1, 0.f);
            float uni = ai + s_ar[j] - inter;
            float u   = fmaxf(uni, 1e-8f);
            float t05 = 0.5f * u;
            if (inter > t05) {
                wordA |= (1u << jj);
                if (inter < t05 * 1.0000002f) wordB |= (1u << jj);
            }
        }
        // Rare exact re-resolution (expected ~0-1 bits per entire run).
        while (wordB) {
            int jj = __ffs(wordB) - 1;
            wordB &= wordB - 1u;
            int j = jbase + jj;
            float4 bj = s_box[j];
            float xx1 = fmaxf(bi.x, bj.x);
            float yy1 = fmaxf(bi.y, bj.y);
            float xx2 = fminf(bi.z, bj.z);
            float yy2 = fminf(bi.w, bj.w);
            float inter = fmaxf(xx2 - xx1, 0.f) * fmaxf(yy2 - yy1, 0.f);
            float uni = ai + s_ar[j] - inter;
            float iou = inter / fmaxf(uni, 1e-8f);
            if (!(iou > NMS_T)) wordA &= ~(1u << jj);
        }
        if (w == (i >> 5)) {
            unsigned sh = (unsigned)(i & 31) + 1u;
            wordA = (sh >= 32u) ? 0u : (wordA & (0xFFFFFFFFu << sh));
        }
        s_sup[i * NWP + w] = wordA;
    }

    // Validity ballot (warps 0..6 cover 224 slots)
    {
        int w = tid >> 5, lane = tid & 31;
        bool val = (tid < PRE) && (s_keys[tid] != 0ULL);
        unsigned bal = __ballot_sync(0xFFFFFFFFu, val);
        if (w < NWORDS && lane == 0) s_keep[w] = bal;
    }
    __syncthreads();

    // Warp 0: chunked greedy NMS resolution + compaction.
    if (tid < 32) {
        int lane = tid;
        unsigned kw = (lane < NWORDS) ? s_keep[lane] : 0u;
        for (int cch = 0; cch < NWORDS; cch++) {
            unsigned cur = __shfl_sync(0xFFFFFFFFu, kw, cch);
            if (lane == 0) {
                unsigned d[32];
#pragma unroll
                for (int jj = 0; jj < 32; jj++)
                    d[jj] = s_sup[(cch * 32 + jj) * NWP + cch];
#pragma unroll
                for (int jj = 0; jj < 32; jj++)
                    if ((cur >> jj) & 1u) cur &= ~d[jj];
            }
            cur = __shfl_sync(0xFFFFFFFFu, cur, 0);
            if (lane == cch) kw = cur;
            if (lane > cch && lane < NWORDS) {
                unsigned acc = 0u;
#pragma unroll
                for (int jj = 0; jj < 32; jj++)
                    if ((cur >> jj) & 1u) acc |= s_sup[(cch * 32 + jj) * NWP + lane];
                kw &= ~acc;
            }
        }
        // Compaction in rank order.
        int offset = 0;
        for (int chunk = 0; chunk < NWORDS; chunk++) {
            unsigned bits = __shfl_sync(0xFFFFFFFFu, kw, chunk);
            int j = chunk * 32 + lane;
            bool kp = (bits >> lane) & 1u;
            if (kp) {
                int rank = offset + __popc(bits & ((1u << lane) - 1u));
                ull key = s_keys[j];
                unsigned n   = ~(unsigned)(key & 0xFFFFFFFFULL);
                unsigned pos = (unsigned)(c * PRE + j);
                g_ckey[pair * PRE + rank] =
                    (key & 0xFFFFFFFF00000000ULL) | (ull)(0xFFFFFFFFu - pos);
                g_nidx[pair * PRE + j] = (int)n;
            }
            offset += __popc(bits);
        }
        if (lane == 0) g_scnt[pair] = offset;
    }
}

// ---------------------------------------------------------------------------
// Pass 3: per image — exact top-100 via sort of first-16-per-class survivor
// keys (with exact saturation check + rare exact fallback), then output.
__global__ void __launch_bounds__(NTW)
k_merge(const float* __restrict__ boxes, const float* __restrict__ rot,
        const float* __restrict__ tr, float* __restrict__ out) {
    __shared__ ull   s_x[CAP];
    __shared__ ull   s_y[CAP];
    __shared__ int   s_scnt[CC];
    __shared__ int   s_ccnt[CC];
    __shared__ int   s_flag;
    __shared__ int   s_idx[MAXDET];
    __shared__ float s_score[MAXDET];
    __shared__ int   s_lab[MAXDET];

    int tid = threadIdx.x;
    int b   = blockIdx.x;

    if (tid == 0) s_flag = 0;
    if (tid < CC) { s_scnt[tid] = g_scnt[b * CC + tid]; s_ccnt[tid] = 0; }
    if (tid < MAXDET) s_idx[tid] = -1;
    __syncthreads();

    // Candidate keys: slot tid -> class tid/16, compacted rank tid%16.
    ull v = 0ULL;
    if (tid < CC * MPC) {
        int cc = tid >> 4, j = tid & 15;
        if (j < s_scnt[cc]) v = g_ckey[(b * CC + cc) * PRE + j];
    }
    sort512w(v, s_x, s_y, tid);
    __syncthreads();
    s_x[tid] = v;                 // descending
    __syncthreads();

    // Saturation check: class contributed all 16 candidates to top-100 while
    // having more survivors -> candidate set may be incomplete -> fallback.
    if (tid < MAXDET) {
        ull key = s_x[tid];
        if (key != 0ULL) {
            unsigned pos = 0xFFFFFFFFu - (unsigned)(key & 0xFFFFFFFFULL);
            atomicAdd(&s_ccnt[pos / PRE], 1);
        }
    }
    __syncthreads();
    if (tid < CC && s_ccnt[tid] >= MPC && s_scnt[tid] > MPC) s_flag = 1;
    __syncthreads();

    if (!s_flag) {
        if (tid < MAXDET) {
            ull key = s_x[tid];
            if (key != 0ULL) {
                unsigned pos = 0xFFFFFFFFu - (unsigned)(key & 0xFFFFFFFFULL);
                int cc = pos / PRE;
                int jo = pos - cc * PRE;
                s_score[tid] = __uint_as_float((unsigned)(key >> 32));
                s_lab[tid]   = cc;
                s_idx[tid]   = g_nidx[(b * CC + cc) * PRE + jo];
            }
        }
    } else if (tid < 32) {
        // Exact fallback: serial 30-way merge over full survivor lists.
        int lane = tid;
        int cnt = 0, ptr = 0;
        ull head = 0ULL;
        if (lane < CC) {
            cnt = s_scnt[lane];
            head = (ptr < cnt) ? g_ckey[(b * CC + lane) * PRE + 0] : 0ULL;
        }
        for (int t = 0; t < MAXDET; t++) {
            ull m = head;
#pragma unroll
            for (int o = 16; o; o >>= 1) {
                ull other = __shfl_xor_sync(0xFFFFFFFFu, m, o);
                if (other > m) m = other;
            }
            if (m == 0ULL) break;
            if (head == m) {
                unsigned pos = 0xFFFFFFFFu - (unsigned)(m & 0xFFFFFFFFULL);
                int jo = pos - lane * PRE;
                s_score[t] = __uint_as_float((unsigned)(m >> 32));
                s_lab[t]   = lane;
                s_idx[t]   = g_nidx[(b * CC + lane) * PRE + jo];
                ptr++;
                head = (ptr < cnt) ? g_ckey[(b * CC + lane) * PRE + ptr] : 0ULL;
            }
        }
    }
    __syncthreads();

    // Output
    for (int t = tid; t < MAXDET; t += NTW) {
        int idx = s_idx[t];
        if (idx >= 0) {
            const float4* bp = reinterpret_cast<const float4*>(boxes);
            float4 bx = __ldg(&bp[(size_t)b * NN + idx]);
            out[OUT_BOXES + (b * MAXDET + t) * 4 + 0] = bx.x;
            out[OUT_BOXES + (b * MAXDET + t) * 4 + 1] = bx.y;
            out[OUT_BOXES + (b * MAXDET + t) * 4 + 2] = bx.z;
            out[OUT_BOXES + (b * MAXDET + t) * 4 + 3] = bx.w;
            out[OUT_SCORES + b * MAXDET + t] = s_score[t];
            out[OUT_LABELS + b * MAXDET + t] = (float)s_lab[t];
            size_t rb = ((size_t)b * NN + idx) * 3;
#pragma unroll
            for (int k = 0; k < 3; k++) {
                out[OUT_ROT + (b * MAXDET + t) * 3 + k] = __ldg(&rot[rb + k]);
                out[OUT_TR  + (b * MAXDET + t) * 3 + k] = __ldg(&tr[rb + k]);
            }
        } else {
#pragma unroll
            for (int k = 0; k < 4; k++)
                out[OUT_BOXES + (b * MAXDET + t) * 4 + k] = -1.0f;
            out[OUT_SCORES + b * MAXDET + t] = -1.0f;
            out[OUT_LABELS + b * MAXDET + t] = -1.0f;
#pragma unroll
            for (int k = 0; k < 3; k++) {
                out[OUT_ROT + (b * MAXDET + t) * 3 + k] = -1.0f;
                out[OUT_TR  + (b * MAXDET + t) * 3 + k] = -1.0f;
            }
        }
    }
}

// ---------------------------------------------------------------------------
extern "C" void kernel_launch(void* const* d_in, const int* in_sizes, int n_in,
                              void* d_out, int out_size) {
    const float* boxes = (const float*)d_in[0];
    const float* cls   = (const float*)d_in[1];
    const float* rot   = (const float*)d_in[2];
    const float* tr    = (const float*)d_in[3];
    float* out = (float*)d_out;

    k_scan<<<SCAN_BLOCKS, 256>>>(cls);
    k_pair<<<PAIRS, NTW>>>(boxes, cls);
    k_merge<<<BB, NTW>>>(boxes, rot, tr, out);
}

// round 15
// speedup vs baseline: 1.0083x; 1.0083x over previous
#include <cuda_runtime.h>
#include <cuda_bf16.h>
#include <stdint.h>

typedef unsigned long long ull;

// Problem constants
#define BB    16
#define NN    100000
#define CC    30
#define NC    (NN * CC)           // 3,000,000
#define TOT   (BB * NC)           // 48,000,000
#define PAIRS (BB * CC)           // 480
#define CAP   512                 // candidate buffer per (b,c)
#define PRE   200                 // PRE_NMS_TOPK
#define MAXDET 100
#define NWORDS 7                  // ceil(200/32)
#define NWP    8                  // padded row stride (words)
#define BOXPAD 224                // padded box count (NWORDS*32)
#define MPC    16                 // merge candidates per class
#define SCAN_BLOCKS 4096
#define NTW   512                 // wide block for pair/merge kernels

#define COLLECT_T    0.997f
#define SCORE_T      0.01f
#define NMS_T        0.5f

// Output layout (flattened float32 concat of the 5 outputs)
#define OUT_BOXES  0
#define OUT_SCORES (BB * MAXDET * 4)
#define OUT_LABELS (OUT_SCORES + BB * MAXDET)
#define OUT_ROT    (OUT_LABELS + BB * MAXDET)
#define OUT_TR     (OUT_ROT + BB * MAXDET * 3)

// Scratch (device globals; zero-initialized at module load)
__device__ ull g_cand[PAIRS * CAP];
__device__ int g_cnt[PAIRS];
__device__ ull g_ckey[PAIRS * PRE];   // survivors by compacted rank
__device__ int g_nidx[PAIRS * PRE];   // anchor index keyed by ORIGINAL rank
__device__ int g_scnt[PAIRS];

// ---------------------------------------------------------------------------
// Dummy kernel: steers the profiler's fixed capture slot (global launch
// index 3) onto k_pair. Does no work; negligible cost.
__global__ void k_nop() {}

// ---------------------------------------------------------------------------
// Pass 1: stream classification, append candidates with score > COLLECT_T.
__device__ __forceinline__ void scan_proc(float4 v, int i4) {
    float m = fmaxf(fmaxf(v.x, v.y), fmaxf(v.z, v.w));
    if (m > COLLECT_T) {
        int base = i4 * 4;
        float vs[4] = {v.x, v.y, v.z, v.w};
#pragma unroll
        for (int k = 0; k < 4; k++) {
            float s = vs[k];
            if (s > COLLECT_T) {
                int i = base + k;
                int b = i / NC;
                int r = i - b * NC;
                int n = r / CC;
                int c = r - n * CC;
                int pair = b * CC + c;
                int pos = atomicAdd(&g_cnt[pair], 1);
                if (pos < CAP) {
                    g_cand[pair * CAP + pos] =
                        ((ull)__float_as_uint(s) << 32) | (unsigned)(~n);
                }
            }
        }
    }
}

__global__ void k_scan(const float* __restrict__ cls) {
    const float4* c4 = reinterpret_cast<const float4*>(cls);
    const int NIT = TOT / 4;
    int T = gridDim.x * blockDim.x;
    int i = blockIdx.x * blockDim.x + threadIdx.x;
    for (; i + 3 * T < NIT; i += 4 * T) {
        float4 a = __ldg(&c4[i]);
        float4 b = __ldg(&c4[i + T]);
        float4 c = __ldg(&c4[i + 2 * T]);
        float4 d = __ldg(&c4[i + 3 * T]);
        scan_proc(a, i);
        scan_proc(b, i + T);
        scan_proc(c, i + 2 * T);
        scan_proc(d, i + 3 * T);
    }
    // Predicated tail: residual loads issued independently (MLP-3).
    {
        bool va = (i < NIT);
        bool vb = (i + T < NIT);
        bool vc = (i + 2 * T < NIT);
        float4 a, b, c;
        if (va) a = __ldg(&c4[i]);
        if (vb) b = __ldg(&c4[i + T]);
        if (vc) c = __ldg(&c4[i + 2 * T]);
        if (va) scan_proc(a, i);
        if (vb) scan_proc(b, i + T);
        if (vc) scan_proc(c, i + 2 * T);
    }
}

// ---------------------------------------------------------------------------
// Bitonic sort of 512 u64 keys with 512 threads, ONE element per thread.
// After return, v = key at rank tid (descending). Ping-pong buffers give
// ONE __syncthreads per smem stage: a later write to buffer X cannot race an
// earlier read of X because that read happens-before the intervening stage's
// sync, which all threads passed.
__device__ __forceinline__ void sort512w(ull& v, ull* bufA, ull* bufB, int tid) {
    int pp = 0;
#pragma unroll
    for (int k2 = 2; k2 <= 512; k2 <<= 1) {
#pragma unroll
        for (int j = k2 >> 1; j > 0; j >>= 1) {
            bool up = (tid & j) != 0;
            bool d  = ((tid & k2) == 0);
            ull o;
            if (j >= 32) {
                ull* buf = pp ? bufB : bufA;
                buf[tid] = v;
                __syncthreads();
                o = buf[tid ^ j];
                pp ^= 1;
            } else {
                o = __shfl_xor_sync(0xFFFFFFFFu, v, j);
            }
            v = (up == d) ? (v < o ? v : o) : (v > o ? v : o);
        }
    }
}

// ---------------------------------------------------------------------------
// Pass 2: per (b,c): exact top-200 sort + greedy NMS + compaction. 512 thr.
__global__ void __launch_bounds__(NTW)
k_pair(const float* __restrict__ boxes, const float* __restrict__ cls) {
    __shared__ ull     s_x[CAP];
    __shared__ ull     s_y[CAP];
    __shared__ ull     s_keys[PRE];
    __shared__ float4  s_box[BOXPAD];
    __shared__ float   s_ar[BOXPAD];
    __shared__ unsigned s_sup[BOXPAD * NWP];
    __shared__ unsigned s_keep[NWORDS];
    __shared__ int     s_M;

    int tid  = threadIdx.x;
    int pair = blockIdx.x;
    int b    = pair / CC;
    int c    = pair - b * CC;

    if (tid == 0) { s_M = g_cnt[pair]; g_cnt[pair] = 0; }
    __syncthreads();
    int M = s_M;

    if (M >= PRE && M <= CAP) {
        ull v = (tid < M) ? g_cand[pair * CAP + tid] : 0ULL;
        sort512w(v, s_x, s_y, tid);
        if (tid < PRE) s_keys[tid] = v;
    } else {
        // Exact fallback (statistically never taken): repeated bounded
        // argmax over the full column with the reference SCORE_T mask.
        ull prev = 0xFFFFFFFFFFFFFFFFULL;
        for (int k = 0; k < PRE; k++) {
            ull best = 0ULL;
            for (int n = tid; n < NN; n += NTW) {
                float s = cls[(size_t)(b * NN + n) * CC + c];
                if (s > SCORE_T) {
                    ull key = ((ull)__float_as_uint(s) << 32) | (unsigned)(~n);
                    if (key < prev && key > best) best = key;
                }
            }
            s_x[tid] = best;
            __syncthreads();
            for (int st = 256; st > 0; st >>= 1) {
                if (tid < st && s_x[tid + st] > s_x[tid]) s_x[tid] = s_x[tid + st];
                __syncthreads();
            }
            if (tid == 0) s_keys[k] = s_x[0];
            prev = s_x[0];
            __syncthreads();
        }
    }
    __syncthreads();

    // Gather top-200 boxes; pad rows [PRE, BOXPAD) with zero-boxes.
    // A zero-box never produces a suppression bit: inter = 0, and
    // 0 > 0.5*max(uni, 1e-8) is false — so the padded columns are inert
    // and the per-iteration j<PRE check can be dropped.
    if (tid < BOXPAD) {
        ull key = (tid < PRE) ? s_keys[tid] : 0ULL;
        if (key != 0ULL) {
            unsigned n = ~(unsigned)(key & 0xFFFFFFFFULL);
            const float4* bp = reinterpret_cast<const float4*>(boxes);
            float4 bx = __ldg(&bp[(size_t)b * NN + n]);
            s_box[tid] = bx;
            s_ar[tid]  = fmaxf(bx.z - bx.x, 0.f) * fmaxf(bx.w - bx.y, 0.f);
        } else {
            s_box[tid] = make_float4(0.f, 0.f, 0.f, 0.f);
            s_ar[tid]  = 0.f;
        }
    }
    __syncthreads();

    // Suppression bit matrix: bit (i, j) iff j>i && j<PRE && iou>0.5.
    // 872 flat (word, row) tasks with w >= row>>5. Division-free hot loop:
    // iou > 0.5 <=> inter > 0.5*u exactly, except the 1-ulp window where the
    // rounded division may land on exactly 0.5; those rare bits are collected
    // in wordB and re-resolved with the original exact-division expression.
    // j>i applied as a post-loop mask on diagonal words only.
    for (int t = tid; t < 872; t += NTW) {
        int w, i;
        if      (t < 32)  { w = 0; i = t; }
        else if (t < 96)  { w = 1; i = t - 32; }
        else if (t < 192) { w = 2; i = t - 96; }
        else if (t < 320) { w = 3; i = t - 192; }
        else if (t < 480) { w = 4; i = t - 320; }
        else if (t < 672) { w = 5; i = t - 480; }
        else              { w = 6; i = t - 672; }
        float4 bi = s_box[i];
        float ai = s_ar[i];
        unsigned wordA = 0u, wordB = 0u;
        int jbase = w * 32;
#pragma unroll 4
        for (int jj = 0; jj < 32; jj++) {
            int j = jbase + jj;
            float4 bj = s_box[j];
            float xx1 = fmaxf(bi.x, bj.x);
            float yy1 = fmaxf(bi.y, bj.y);
            float xx2 = fminf(bi.z, bj.z);
            float yy2 = fminf(bi.w, bj.w);
            float inter = fmaxf(xx2 - xx1, 0.f) * fmaxf(yy2 - yy1, 0.f);
            float uni = ai + s_ar[j] - inter;
            float u   = fmaxf(uni, 1e-8f);
            float t05 = 0.5f * u;
            if (inter > t05) {
                wordA |= (1u << jj);
                if (inter < t05 * 1.0000002f) wordB |= (1u << jj);
            }
        }
        // Rare exact re-resolution (expected ~0-1 bits per entire run).
        while (wordB) {
            int jj = __ffs(wordB) - 1;
            wordB &= wordB - 1u;
            int j = jbase + jj;
            float4 bj = s_box[j];
            float xx1 = fmaxf(bi.x, bj.x);
            float yy1 = fmaxf(bi.y, bj.y);
            float xx2 = fminf(bi.z, bj.z);
            float yy2 = fminf(bi.w, bj.w);
            float inter = fmaxf(xx2 - xx1, 0.f) * fmaxf(yy2 - yy1, 0.f);
            float uni = ai + s_ar[j] - inter;
            float iou = inter / fmaxf(uni, 1e-8f);
            if (!(iou > NMS_T)) wordA &= ~(1u << jj);
        }
        if (w == (i >> 5)) {
            unsigned sh = (unsigned)(i & 31) + 1u;
            wordA = (sh >= 32u) ? 0u : (wordA & (0xFFFFFFFFu << sh));
        }
        s_sup[i * NWP + w] = wordA;
    }

    // Validity ballot (warps 0..6 cover 224 slots)
    {
        int w = tid >> 5, lane = tid & 31;
        bool val = (tid < PRE) && (s_keys[tid] != 0ULL);
        unsigned bal = __ballot_sync(0xFFFFFFFFu, val);
        if (w < NWORDS && lane == 0) s_keep[w] = bal;
    }
    __syncthreads();

    // Warp 0: chunked greedy NMS resolution + compaction.
    if (tid < 32) {
        int lane = tid;
        unsigned kw = (lane < NWORDS) ? s_keep[lane] : 0u;
        for (int cch = 0; cch < NWORDS; cch++) {
            unsigned cur = __shfl_sync(0xFFFFFFFFu, kw, cch);
            if (lane == 0) {
                unsigned d[32];
#pragma unroll
                for (int jj = 0; jj < 32; jj++)
                    d[jj] = s_sup[(cch * 32 + jj) * NWP + cch];
#pragma unroll
                for (int jj = 0; jj < 32; jj++)
                    if ((cur >> jj) & 1u) cur &= ~d[jj];
            }
            cur = __shfl_sync(0xFFFFFFFFu, cur, 0);
            if (lane == cch) kw = cur;
            if (lane > cch && lane < NWORDS) {
                unsigned acc = 0u;
#pragma unroll
                for (int jj = 0; jj < 32; jj++)
                    if ((cur >> jj) & 1u) acc |= s_sup[(cch * 32 + jj) * NWP + lane];
                kw &= ~acc;
            }
        }
        // Compaction in rank order.
        int offset = 0;
        for (int chunk = 0; chunk < NWORDS; chunk++) {
            unsigned bits = __shfl_sync(0xFFFFFFFFu, kw, chunk);
            int j = chunk * 32 + lane;
            bool kp = (bits >> lane) & 1u;
            if (kp) {
                int rank = offset + __popc(bits & ((1u << lane) - 1u));
                ull key = s_keys[j];
                unsigned n   = ~(unsigned)(key & 0xFFFFFFFFULL);
                unsigned pos = (unsigned)(c * PRE + j);
                g_ckey[pair * PRE + rank] =
                    (key & 0xFFFFFFFF00000000ULL) | (ull)(0xFFFFFFFFu - pos);
                g_nidx[pair * PRE + j] = (int)n;
            }
            offset += __popc(bits);
        }
        if (lane == 0) g_scnt[pair] = offset;
    }
}

// ---------------------------------------------------------------------------
// Pass 3: per image — exact top-100 via sort of first-16-per-class survivor
// keys (with exact saturation check + rare exact fallback), then output.
__global__ void __launch_bounds__(NTW)
k_merge(const float* __restrict__ boxes, const float* __restrict__ rot,
        const float* __restrict__ tr, float* __restrict__ out) {
    __shared__ ull   s_x[CAP];
    __shared__ ull   s_y[CAP];
    __shared__ int   s_scnt[CC];
    __shared__ int   s_ccnt[CC];
    __shared__ int   s_flag;
    __shared__ int   s_idx[MAXDET];
    __shared__ float s_score[MAXDET];
    __shared__ int   s_lab[MAXDET];

    int tid = threadIdx.x;
    int b   = blockIdx.x;

    if (tid == 0) s_flag = 0;
    if (tid < CC) { s_scnt[tid] = g_scnt[b * CC + tid]; s_ccnt[tid] = 0; }
    if (tid < MAXDET) s_idx[tid] = -1;
    __syncthreads();

    // Candidate keys: slot tid -> class tid/16, compacted rank tid%16.
    ull v = 0ULL;
    if (tid < CC * MPC) {
        int cc = tid >> 4, j = tid & 15;
        if (j < s_scnt[cc]) v = g_ckey[(b * CC + cc) * PRE + j];
    }
    sort512w(v, s_x, s_y, tid);
    __syncthreads();
    s_x[tid] = v;                 // descending
    __syncthreads();

    // Saturation check: class contributed all 16 candidates to top-100 while
    // having more survivors -> candidate set may be incomplete -> fallback.
    if (tid < MAXDET) {
        ull key = s_x[tid];
        if (key != 0ULL) {
            unsigned pos = 0xFFFFFFFFu - (unsigned)(key & 0xFFFFFFFFULL);
            atomicAdd(&s_ccnt[pos / PRE], 1);
        }
    }
    __syncthreads();
    if (tid < CC && s_ccnt[tid] >= MPC && s_scnt[tid] > MPC) s_flag = 1;
    __syncthreads();

    if (!s_flag) {
        if (tid < MAXDET) {
            ull key = s_x[tid];
            if (key != 0ULL) {
                unsigned pos = 0xFFFFFFFFu - (unsigned)(key & 0xFFFFFFFFULL);
                int cc = pos / PRE;
                int jo = pos - cc * PRE;
                s_score[tid] = __uint_as_float((unsigned)(key >> 32));
                s_lab[tid]   = cc;
                s_idx[tid]   = g_nidx[(b * CC + cc) * PRE + jo];
            }
        }
    } else if (tid < 32) {
        // Exact fallback: serial 30-way merge over full survivor lists.
        int lane = tid;
        int cnt = 0, ptr = 0;
        ull head = 0ULL;
        if (lane < CC) {
            cnt = s_scnt[lane];
            head = (ptr < cnt) ? g_ckey[(b * CC + lane) * PRE + 0] : 0ULL;
        }
        for (int t = 0; t < MAXDET; t++) {
            ull m = head;
#pragma unroll
            for (int o = 16; o; o >>= 1) {
                ull other = __shfl_xor_sync(0xFFFFFFFFu, m, o);
                if (other > m) m = other;
            }
            if (m == 0ULL) break;
            if (head == m) {
                unsigned pos = 0xFFFFFFFFu - (unsigned)(m & 0xFFFFFFFFULL);
                int jo = pos - lane * PRE;
                s_score[t] = __uint_as_float((unsigned)(m >> 32));
                s_lab[t]   = lane;
                s_idx[t]   = g_nidx[(b * CC + lane) * PRE + jo];
                ptr++;
                head = (ptr < cnt) ? g_ckey[(b * CC + lane) * PRE + ptr] : 0ULL;
            }
        }
    }
    __syncthreads();

    // Output
    for (int t = tid; t < MAXDET; t += NTW) {
        int idx = s_idx[t];
        if (idx >= 0) {
            const float4* bp = reinterpret_cast<const float4*>(boxes);
            float4 bx = __ldg(&bp[(size_t)b * NN + idx]);
            out[OUT_BOXES + (b * MAXDET + t) * 4 + 0] = bx.x;
            out[OUT_BOXES + (b * MAXDET + t) * 4 + 1] = bx.y;
            out[OUT_BOXES + (b * MAXDET + t) * 4 + 2] = bx.z;
            out[OUT_BOXES + (b * MAXDET + t) * 4 + 3] = bx.w;
            out[OUT_SCORES + b * MAXDET + t] = s_score[t];
            out[OUT_LABELS + b * MAXDET + t] = (float)s_lab[t];
            size_t rb = ((size_t)b * NN + idx) * 3;
#pragma unroll
            for (int k = 0; k < 3; k++) {
                out[OUT_ROT + (b * MAXDET + t) * 3 + k] = __ldg(&rot[rb + k]);
                out[OUT_TR  + (b * MAXDET + t) * 3 + k] = __ldg(&tr[rb + k]);
            }
        } else {
#pragma unroll
            for (int k = 0; k < 4; k++)
                out[OUT_BOXES + (b * MAXDET + t) * 4 + k] = -1.0f;
            out[OUT_SCORES + b * MAXDET + t] = -1.0f;
            out[OUT_LABELS + b * MAXDET + t] = -1.0f;
#pragma unroll
            for (int k = 0; k < 3; k++) {
                out[OUT_ROT + (b * MAXDET + t) * 3 + k] = -1.0f;
                out[OUT_TR  + (b * MAXDET + t) * 3 + k] = -1.0f;
            }
        }
    }
}

// ---------------------------------------------------------------------------
extern "C" void kernel_launch(void* const* d_in, const int* in_sizes, int n_in,
                              void* d_out, int out_size) {
    const float* boxes = (const float*)d_in[0];
    const float* cls   = (const float*)d_in[1];
    const float* rot   = (const float*)d_in[2];
    const float* tr    = (const float*)d_in[3];
    float* out = (float*)d_out;

    k_scan<<<SCAN_BLOCKS, 256>>>(cls);
    k_nop<<<1, 32>>>();                 // capture-slot shims: put k_pair at
    k_nop<<<1, 32>>>();                 // global launch index 3 (ncu -s 5 -c 1)
    k_pair<<<PAIRS, NTW>>>(boxes, cls);
    k_merge<<<BB, NTW>>>(boxes, rot, tr, out);
}

// round 16
// speedup vs baseline: 1.0541x; 1.0454x over previous
#include <cuda_runtime.h>
#include <cuda_bf16.h>
#include <stdint.h>

typedef unsigned long long ull;

// Problem constants
#define BB    16
#define NN    100000
#define CC    30
#define NC    (NN * CC)           // 3,000,000
#define TOT   (BB * NC)           // 48,000,000
#define PAIRS (BB * CC)           // 480
#define CAP   512                 // candidate buffer per (b,c)
#define PRE   200                 // PRE_NMS_TOPK
#define MAXDET 100
#define NWORDS 7                  // ceil(200/32)
#define NWP    8                  // padded row stride (words)
#define BOXPAD 224                // padded box count (NWORDS*32)
#define MPC    16                 // merge candidates per class
#define SCAN_BLOCKS 4096
#define NTW   512                 // wide block for pair/merge kernels

#define COLLECT_T    0.997f
#define SCORE_T      0.01f
#define NMS_T        0.5f

// Output layout (flattened float32 concat of the 5 outputs)
#define OUT_BOXES  0
#define OUT_SCORES (BB * MAXDET * 4)
#define OUT_LABELS (OUT_SCORES + BB * MAXDET)
#define OUT_ROT    (OUT_LABELS + BB * MAXDET)
#define OUT_TR     (OUT_ROT + BB * MAXDET * 3)

// Scratch (device globals; zero-initialized at module load)
__device__ ull g_cand[PAIRS * CAP];
__device__ int g_cnt[PAIRS];
__device__ ull g_ckey[PAIRS * PRE];   // survivors by compacted rank
__device__ int g_nidx[PAIRS * PRE];   // anchor index keyed by ORIGINAL rank
__device__ int g_scnt[PAIRS];

// ---------------------------------------------------------------------------
// Pass 1: stream classification, append candidates with score > COLLECT_T.
__device__ __forceinline__ void scan_proc(float4 v, int i4) {
    float m = fmaxf(fmaxf(v.x, v.y), fmaxf(v.z, v.w));
    if (m > COLLECT_T) {
        int base = i4 * 4;
        float vs[4] = {v.x, v.y, v.z, v.w};
#pragma unroll
        for (int k = 0; k < 4; k++) {
            float s = vs[k];
            if (s > COLLECT_T) {
                int i = base + k;
                int b = i / NC;
                int r = i - b * NC;
                int n = r / CC;
                int c = r - n * CC;
                int pair = b * CC + c;
                int pos = atomicAdd(&g_cnt[pair], 1);
                if (pos < CAP) {
                    g_cand[pair * CAP + pos] =
                        ((ull)__float_as_uint(s) << 32) | (unsigned)(~n);
                }
            }
        }
    }
}

__global__ void k_scan(const float* __restrict__ cls) {
    const float4* c4 = reinterpret_cast<const float4*>(cls);
    const int NIT = TOT / 4;
    int T = gridDim.x * blockDim.x;
    int i = blockIdx.x * blockDim.x + threadIdx.x;
    for (; i + 3 * T < NIT; i += 4 * T) {
        float4 a = __ldg(&c4[i]);
        float4 b = __ldg(&c4[i + T]);
        float4 c = __ldg(&c4[i + 2 * T]);
        float4 d = __ldg(&c4[i + 3 * T]);
        scan_proc(a, i);
        scan_proc(b, i + T);
        scan_proc(c, i + 2 * T);
        scan_proc(d, i + 3 * T);
    }
    // Predicated tail: residual loads issued independently (MLP-3).
    {
        bool va = (i < NIT);
        bool vb = (i + T < NIT);
        bool vc = (i + 2 * T < NIT);
        float4 a, b, c;
        if (va) a = __ldg(&c4[i]);
        if (vb) b = __ldg(&c4[i + T]);
        if (vc) c = __ldg(&c4[i + 2 * T]);
        if (va) scan_proc(a, i);
        if (vb) scan_proc(b, i + T);
        if (vc) scan_proc(c, i + 2 * T);
    }
}

// ---------------------------------------------------------------------------
// Bitonic sort of 512 u64 keys with 512 threads, ONE element per thread.
// After return, v = key at rank tid (descending). Ping-pong buffers give
// ONE __syncthreads per smem stage (write of X cannot race earlier read of X
// because that read happens-before the intervening stage's sync).
__device__ __forceinline__ void sort512w(ull& v, ull* bufA, ull* bufB, int tid) {
    int pp = 0;
#pragma unroll
    for (int k2 = 2; k2 <= 512; k2 <<= 1) {
#pragma unroll
        for (int j = k2 >> 1; j > 0; j >>= 1) {
            bool up = (tid & j) != 0;
            bool d  = ((tid & k2) == 0);
            ull o;
            if (j >= 32) {
                ull* buf = pp ? bufB : bufA;
                buf[tid] = v;
                __syncthreads();
                o = buf[tid ^ j];
                pp ^= 1;
            } else {
                o = __shfl_xor_sync(0xFFFFFFFFu, v, j);
            }
            v = (up == d) ? (v < o ? v : o) : (v > o ? v : o);
        }
    }
}

// ---------------------------------------------------------------------------
// Pass 2: per (b,c): exact top-200 sort + greedy NMS + compaction. 512 thr.
__global__ void __launch_bounds__(NTW)
k_pair(const float* __restrict__ boxes, const float* __restrict__ cls) {
    __shared__ ull     s_x[CAP];
    __shared__ ull     s_y[CAP];
    __shared__ ull     s_keys[PRE];
    __shared__ float4  s_box[BOXPAD];
    __shared__ float   s_ar[BOXPAD];
    __shared__ unsigned s_sup[BOXPAD * NWP];
    __shared__ unsigned s_keep[NWORDS];
    __shared__ int     s_M;

    int tid  = threadIdx.x;
    int pair = blockIdx.x;
    int b    = pair / CC;
    int c    = pair - b * CC;

    if (tid == 0) { s_M = g_cnt[pair]; g_cnt[pair] = 0; }
    __syncthreads();
    int M = s_M;

    if (M >= PRE && M <= CAP) {
        ull v = (tid < M) ? g_cand[pair * CAP + tid] : 0ULL;
        sort512w(v, s_x, s_y, tid);
        if (tid < PRE) s_keys[tid] = v;
    } else {
        // Exact fallback (statistically never taken): repeated bounded
        // argmax over the full column with the reference SCORE_T mask.
        ull prev = 0xFFFFFFFFFFFFFFFFULL;
        for (int k = 0; k < PRE; k++) {
            ull best = 0ULL;
            for (int n = tid; n < NN; n += NTW) {
                float s = cls[(size_t)(b * NN + n) * CC + c];
                if (s > SCORE_T) {
                    ull key = ((ull)__float_as_uint(s) << 32) | (unsigned)(~n);
                    if (key < prev && key > best) best = key;
                }
            }
            s_x[tid] = best;
            __syncthreads();
            for (int st = 256; st > 0; st >>= 1) {
                if (tid < st && s_x[tid + st] > s_x[tid]) s_x[tid] = s_x[tid + st];
                __syncthreads();
            }
            if (tid == 0) s_keys[k] = s_x[0];
            prev = s_x[0];
            __syncthreads();
        }
    }
    __syncthreads();

    // Gather top-200 boxes; pad rows [PRE, BOXPAD) with zero-boxes (inert:
    // zero inter can never exceed 0.5*max(uni,1e-8), so no suppression bit).
    if (tid < BOXPAD) {
        ull key = (tid < PRE) ? s_keys[tid] : 0ULL;
        if (key != 0ULL) {
            unsigned n = ~(unsigned)(key & 0xFFFFFFFFULL);
            const float4* bp = reinterpret_cast<const float4*>(boxes);
            float4 bx = __ldg(&bp[(size_t)b * NN + n]);
            s_box[tid] = bx;
            s_ar[tid]  = fmaxf(bx.z - bx.x, 0.f) * fmaxf(bx.w - bx.y, 0.f);
        } else {
            s_box[tid] = make_float4(0.f, 0.f, 0.f, 0.f);
            s_ar[tid]  = 0.f;
        }
    }
    __syncthreads();

    // Suppression bit matrix: bit (i, j) iff j>i && j<PRE && iou>0.5.
    // TWO rows per task: task (w, p) covers rows (2p, 2p+1) for word w, with
    // w >= p>>4 (upper triangle at word granularity). 448 tasks; each j-iter
    // loads s_box[j]/s_ar[j] ONCE (warp-broadcast) and evaluates both rows.
    // Division-free: iou>0.5 <=> inter>0.5*u exactly except the 1-ulp window
    // where the rounded division may land on exactly 0.5; those rare bits go
    // to wB* and are re-resolved with the exact-division expression.
    if (tid < 448) {
        int t = tid, w, p;
        if      (t < 16)  { w = 0; p = t; }
        else if (t < 48)  { w = 1; p = t - 16; }
        else if (t < 96)  { w = 2; p = t - 48; }
        else if (t < 160) { w = 3; p = t - 96; }
        else if (t < 240) { w = 4; p = t - 160; }
        else if (t < 336) { w = 5; p = t - 240; }
        else              { w = 6; p = t - 336; }
        int i0 = 2 * p, i1 = 2 * p + 1;
        float4 b0 = s_box[i0]; float a0 = s_ar[i0];
        float4 b1 = s_box[i1]; float a1 = s_ar[i1];
        unsigned wA0 = 0u, wB0 = 0u, wA1 = 0u, wB1 = 0u;
        int jbase = w * 32;
#pragma unroll 4
        for (int jj = 0; jj < 32; jj++) {
            int j = jbase + jj;
            float4 bj = s_box[j];
            float aj = s_ar[j];
            {
                float xx1 = fmaxf(b0.x, bj.x);
                float yy1 = fmaxf(b0.y, bj.y);
                float xx2 = fminf(b0.z, bj.z);
                float yy2 = fminf(b0.w, bj.w);
                float inter = fmaxf(xx2 - xx1, 0.f) * fmaxf(yy2 - yy1, 0.f);
                float u   = fmaxf(a0 + aj - inter, 1e-8f);
                float t05 = 0.5f * u;
                if (inter > t05) {
                    wA0 |= (1u << jj);
                    if (inter < t05 * 1.0000002f) wB0 |= (1u << jj);
                }
            }
            {
                float xx1 = fmaxf(b1.x, bj.x);
                float yy1 = fmaxf(b1.y, bj.y);
                float xx2 = fminf(b1.z, bj.z);
                float yy2 = fminf(b1.w, bj.w);
                float inter = fmaxf(xx2 - xx1, 0.f) * fmaxf(yy2 - yy1, 0.f);
                float u   = fmaxf(a1 + aj - inter, 1e-8f);
                float t05 = 0.5f * u;
                if (inter > t05) {
                    wA1 |= (1u << jj);
                    if (inter < t05 * 1.0000002f) wB1 |= (1u << jj);
                }
            }
        }
        // Rare exact re-resolution (expected ~0-1 bits per entire run).
        while (wB0) {
            int jj = __ffs(wB0) - 1;
            wB0 &= wB0 - 1u;
            int j = jbase + jj;
            float4 bj = s_box[j];
            float xx1 = fmaxf(b0.x, bj.x), yy1 = fmaxf(b0.y, bj.y);
            float xx2 = fminf(b0.z, bj.z), yy2 = fminf(b0.w, bj.w);
            float inter = fmaxf(xx2 - xx1, 0.f) * fmaxf(yy2 - yy1, 0.f);
            float iou = inter / fmaxf(a0 + s_ar[j] - inter, 1e-8f);
            if (!(iou > NMS_T)) wA0 &= ~(1u << jj);
        }
        while (wB1) {
            int jj = __ffs(wB1) - 1;
            wB1 &= wB1 - 1u;
            int j = jbase + jj;
            float4 bj = s_box[j];
            float xx1 = fmaxf(b1.x, bj.x), yy1 = fmaxf(b1.y, bj.y);
            float xx2 = fminf(b1.z, bj.z), yy2 = fminf(b1.w, bj.w);
            float inter = fmaxf(xx2 - xx1, 0.f) * fmaxf(yy2 - yy1, 0.f);
            float iou = inter / fmaxf(a1 + s_ar[j] - inter, 1e-8f);
            if (!(iou > NMS_T)) wA1 &= ~(1u << jj);
        }
        // j>i masks on the diagonal word only (i0, i1 share the same chunk).
        if (w == (i0 >> 5)) {
            unsigned sh0 = (unsigned)(i0 & 31) + 1u;
            wA0 = (sh0 >= 32u) ? 0u : (wA0 & (0xFFFFFFFFu << sh0));
            unsigned sh1 = (unsigned)(i1 & 31) + 1u;
            wA1 = (sh1 >= 32u) ? 0u : (wA1 & (0xFFFFFFFFu << sh1));
        }
        s_sup[i0 * NWP + w] = wA0;
        s_sup[i1 * NWP + w] = wA1;
    }

    // Validity ballot (warps 0..6 cover 224 slots)
    {
        int w = tid >> 5, lane = tid & 31;
        bool val = (tid < PRE) && (s_keys[tid] != 0ULL);
        unsigned bal = __ballot_sync(0xFFFFFFFFu, val);
        if (w < NWORDS && lane == 0) s_keep[w] = bal;
    }
    __syncthreads();

    // Warp 0: chunked greedy NMS resolution + compaction.
    if (tid < 32) {
        int lane = tid;
        unsigned kw = (lane < NWORDS) ? s_keep[lane] : 0u;
        for (int cch = 0; cch < NWORDS; cch++) {
            unsigned cur = __shfl_sync(0xFFFFFFFFu, kw, cch);
            if (lane == 0) {
                unsigned d[32];
#pragma unroll
                for (int jj = 0; jj < 32; jj++)
                    d[jj] = s_sup[(cch * 32 + jj) * NWP + cch];
#pragma unroll
                for (int jj = 0; jj < 32; jj++)
                    if ((cur >> jj) & 1u) cur &= ~d[jj];
            }
            cur = __shfl_sync(0xFFFFFFFFu, cur, 0);
            if (lane == cch) kw = cur;
            if (lane > cch && lane < NWORDS) {
                unsigned acc = 0u;
#pragma unroll
                for (int jj = 0; jj < 32; jj++)
                    if ((cur >> jj) & 1u) acc |= s_sup[(cch * 32 + jj) * NWP + lane];
                kw &= ~acc;
            }
        }
        // Compaction in rank order.
        int offset = 0;
        for (int chunk = 0; chunk < NWORDS; chunk++) {
            unsigned bits = __shfl_sync(0xFFFFFFFFu, kw, chunk);
            int j = chunk * 32 + lane;
            bool kp = (bits >> lane) & 1u;
            if (kp) {
                int rank = offset + __popc(bits & ((1u << lane) - 1u));
                ull key = s_keys[j];
                unsigned n   = ~(unsigned)(key & 0xFFFFFFFFULL);
                unsigned pos = (unsigned)(c * PRE + j);
                g_ckey[pair * PRE + rank] =
                    (key & 0xFFFFFFFF00000000ULL) | (ull)(0xFFFFFFFFu - pos);
                g_nidx[pair * PRE + j] = (int)n;
            }
            offset += __popc(bits);
        }
        if (lane == 0) g_scnt[pair] = offset;
    }
}

// ---------------------------------------------------------------------------
// Pass 3: per image — exact top-100 via sort of first-16-per-class survivor
// keys (with exact saturation check + rare exact fallback), then output.
__global__ void __launch_bounds__(NTW)
k_merge(const float* __restrict__ boxes, const float* __restrict__ rot,
        const float* __restrict__ tr, float* __restrict__ out) {
    __shared__ ull   s_x[CAP];
    __shared__ ull   s_y[CAP];
    __shared__ int   s_scnt[CC];
    __shared__ int   s_ccnt[CC];
    __shared__ int   s_flag;
    __shared__ int   s_idx[MAXDET];
    __shared__ float s_score[MAXDET];
    __shared__ int   s_lab[MAXDET];

    int tid = threadIdx.x;
    int b   = blockIdx.x;

    if (tid == 0) s_flag = 0;
    if (tid < CC) { s_scnt[tid] = g_scnt[b * CC + tid]; s_ccnt[tid] = 0; }
    if (tid < MAXDET) s_idx[tid] = -1;
    __syncthreads();

    // Candidate keys: slot tid -> class tid/16, compacted rank tid%16.
    ull v = 0ULL;
    if (tid < CC * MPC) {
        int cc = tid >> 4, j = tid & 15;
        if (j < s_scnt[cc]) v = g_ckey[(b * CC + cc) * PRE + j];
    }
    sort512w(v, s_x, s_y, tid);
    __syncthreads();
    s_x[tid] = v;                 // descending
    __syncthreads();

    // Saturation check: class contributed all 16 candidates to top-100 while
    // having more survivors -> candidate set may be incomplete -> fallback.
    if (tid < MAXDET) {
        ull key = s_x[tid];
        if (key != 0ULL) {
            unsigned pos = 0xFFFFFFFFu - (unsigned)(key & 0xFFFFFFFFULL);
            atomicAdd(&s_ccnt[pos / PRE], 1);
        }
    }
    __syncthreads();
    if (tid < CC && s_ccnt[tid] >= MPC && s_scnt[tid] > MPC) s_flag = 1;
    __syncthreads();

    if (!s_flag) {
        if (tid < MAXDET) {
            ull key = s_x[tid];
            if (key != 0ULL) {
                unsigned pos = 0xFFFFFFFFu - (unsigned)(key & 0xFFFFFFFFULL);
                int cc = pos / PRE;
                int jo = pos - cc * PRE;
                s_score[tid] = __uint_as_float((unsigned)(key >> 32));
                s_lab[tid]   = cc;
                s_idx[tid]   = g_nidx[(b * CC + cc) * PRE + jo];
            }
        }
    } else if (tid < 32) {
        // Exact fallback: serial 30-way merge over full survivor lists.
        int lane = tid;
        int cnt = 0, ptr = 0;
        ull head = 0ULL;
        if (lane < CC) {
            cnt = s_scnt[lane];
            head = (ptr < cnt) ? g_ckey[(b * CC + lane) * PRE + 0] : 0ULL;
        }
        for (int t = 0; t < MAXDET; t++) {
            ull m = head;
#pragma unroll
            for (int o = 16; o; o >>= 1) {
                ull other = __shfl_xor_sync(0xFFFFFFFFu, m, o);
                if (other > m) m = other;
            }
            if (m == 0ULL) break;
            if (head == m) {
                unsigned pos = 0xFFFFFFFFu - (unsigned)(m & 0xFFFFFFFFULL);
                int jo = pos - lane * PRE;
                s_score[t] = __uint_as_float((unsigned)(m >> 32));
                s_lab[t]   = lane;
                s_idx[t]   = g_nidx[(b * CC + lane) * PRE + jo];
                ptr++;
                head = (ptr < cnt) ? g_ckey[(b * CC + lane) * PRE + ptr] : 0ULL;
            }
        }
    }
    __syncthreads();

    // Output
    for (int t = tid; t < MAXDET; t += NTW) {
        int idx = s_idx[t];
        if (idx >= 0) {
            const float4* bp = reinterpret_cast<const float4*>(boxes);
            float4 bx = __ldg(&bp[(size_t)b * NN + idx]);
            out[OUT_BOXES + (b * MAXDET + t) * 4 + 0] = bx.x;
            out[OUT_BOXES + (b * MAXDET + t) * 4 + 1] = bx.y;
            out[OUT_BOXES + (b * MAXDET + t) * 4 + 2] = bx.z;
            out[OUT_BOXES + (b * MAXDET + t) * 4 + 3] = bx.w;
            out[OUT_SCORES + b * MAXDET + t] = s_score[t];
            out[OUT_LABELS + b * MAXDET + t] = (float)s_lab[t];
            size_t rb = ((size_t)b * NN + idx) * 3;
#pragma unroll
            for (int k = 0; k < 3; k++) {
                out[OUT_ROT + (b * MAXDET + t) * 3 + k] = __ldg(&rot[rb + k]);
                out[OUT_TR  + (b * MAXDET + t) * 3 + k] = __ldg(&tr[rb + k]);
            }
        } else {
#pragma unroll
            for (int k = 0; k < 4; k++)
                out[OUT_BOXES + (b * MAXDET + t) * 4 + k] = -1.0f;
            out[OUT_SCORES + b * MAXDET + t] = -1.0f;
            out[OUT_LABELS + b * MAXDET + t] = -1.0f;
#pragma unroll
            for (int k = 0; k < 3; k++) {
                out[OUT_ROT + (b * MAXDET + t) * 3 + k] = -1.0f;
                out[OUT_TR  + (b * MAXDET + t) * 3 + k] = -1.0f;
            }
        }
    }
}

// ---------------------------------------------------------------------------
extern "C" void kernel_launch(void* const* d_in, const int* in_sizes, int n_in,
                              void* d_out, int out_size) {
    const float* boxes = (const float*)d_in[0];
    const float* cls   = (const float*)d_in[1];
    const float* rot   = (const float*)d_in[2];
    const float* tr    = (const float*)d_in[3];
    float* out = (float*)d_out;

    k_scan<<<SCAN_BLOCKS, 256>>>(cls);
    k_pair<<<PAIRS, NTW>>>(boxes, cls);
    k_merge<<<BB, NTW>>>(boxes, rot, tr, out);
}